// round 5
// baseline (speedup 1.0000x reference)
#include <cuda_runtime.h>
#include <cstdint>

#define BATCH 4
#define CIN   64
#define COUT  64
#define HW    224
#define NPIX  (HW * HW)          // 50176
#define KK    9
#define NBINS 10
#define KTOT  (CIN * KK)         // 576
#define KC    32
#define NCHUNK (KTOT / KC)       // 18
#define TILE_M 128
#define NTILE (NPIX / TILE_M)    // 392
#define NCONV (BATCH * NTILE)    // 1568
#define NHIST (BATCH * CIN * 4)  // 1024
#define NBLK  (NCONV + NHIST)    // 2592
#define Y_ELEMS (BATCH * COUT * NPIX)
#define ESTRIDE 132              // epilogue smem stride (conflict-free)

// B fragments, tf32 bits, layout [chunk][nt 8][ks 4][lane 32][2]
__device__ uint32_t g_wfrag[NCHUNK * 2048];
__device__ int g_hist_i[CIN * NBINS];

__device__ __forceinline__ uint32_t f2tf32(float v) {
    uint32_t u;
    asm("cvt.rna.tf32.f32 %0, %1;" : "=r"(u) : "f"(v));
    return u;
}

#define MMA_TF32(d, a, b) \
    asm volatile("mma.sync.aligned.m16n8k8.row.col.f32.tf32.tf32.f32 " \
        "{%0,%1,%2,%3}, {%4,%5,%6,%7}, {%8,%9}, {%0,%1,%2,%3};" \
        : "+f"((d)[0]), "+f"((d)[1]), "+f"((d)[2]), "+f"((d)[3]) \
        : "r"((a).x), "r"((a).y), "r"((a).z), "r"((a).w), \
          "r"((b).x), "r"((b).y))

// ---------------------------------------------------------------------------
// Repack W (64, 576) -> fragment order (tf32-rounded) + zero hist scratch.
// ---------------------------------------------------------------------------
__global__ void repack_w_kernel(const float* __restrict__ w) {
    int idx = blockIdx.x * blockDim.x + threadIdx.x;
    if (idx < NCHUNK * 2048) {
        int pair = idx & 1;
        int lane = (idx >> 1) & 31;
        int ks   = (idx >> 6) & 3;
        int nt   = (idx >> 8) & 7;
        int c    = idx >> 11;
        int n = nt * 8 + (lane >> 2);
        int k = c * 32 + ks * 8 + (lane & 3) + pair * 4;
        g_wfrag[idx] = f2tf32(__ldg(&w[n * KTOT + k]));
    }
    if (idx < CIN * NBINS) g_hist_i[idx] = 0;
}

// ---------------------------------------------------------------------------
// hist helper: horizontal 3-window zero counts for 4 columns, packed bytes
// ---------------------------------------------------------------------------
__device__ __forceinline__ unsigned zprow_calc(unsigned nib, int l) {
    unsigned nl = __shfl_sync(0xFFFFFFFFu, nib, (l == 0) ? 29 : (l - 1));
    unsigned nr = __shfl_sync(0xFFFFFFFFu, nib, (l == 27) ? 28 : ((l + 1) & 31));
    unsigned ext = ((nl >> 3) & 1u) | (nib << 1) | ((nr & 1u) << 5);
    unsigned z0 = __popc(ext & 7u);
    unsigned z1 = __popc((ext >> 1) & 7u);
    unsigned z2 = __popc((ext >> 2) & 7u);
    unsigned z3 = __popc((ext >> 3) & 7u);
    return z0 | (z1 << 8) | (z2 << 16) | (z3 << 24);
}

struct ConvShared {
    uint32_t sA[2][4224];     // frag A double-buffer; reused for epilogue stage
    int   tab[KTOT];
    float sbias[COUT];
};
struct HistShared { int sbin[NBINS]; };

// ---------------------------------------------------------------------------
// Fused kernel: conv blocks (implicit-GEMM tf32 mma.sync) + hist blocks.
// ---------------------------------------------------------------------------
__global__ __launch_bounds__(256, 2)
void fused_kernel(const float* __restrict__ x,
                  const float* __restrict__ wgt,
                  const float* __restrict__ bias,
                  float* __restrict__ y) {
    __shared__ __align__(16) union { ConvShared c; HistShared h; } sm;

    const int bid = blockIdx.x;
    const int tid = threadIdx.x;

    // ---- interleave remap: per 5 bids -> 2 hist + 3 conv ----
    int cidx = 0, hidx = 0;
    bool is_hist = false;
    if (bid < 2560) {
        int q = bid / 5, r = bid % 5;
        if (r < 2) { is_hist = true; hidx = q * 2 + r; }
        else       { cidx = q * 3 + (r - 2); }
    } else {
        cidx = 1536 + (bid - 2560);
    }

    if (is_hist) {
        // ================= HIST BLOCK =================
        const int rc = hidx & 3;
        const int c  = (hidx >> 2) & 63;
        const int b  = hidx >> 8;
        int* sbin = sm.h.sbin;
        if (tid < NBINS) sbin[tid] = 0;

        bool anywz = false;
        #pragma unroll
        for (int k = 0; k < KK; k++) anywz |= (__ldg(&wgt[c * KK + k]) == 0.0f);
        __syncthreads();

        const float* xp = x + (size_t)(b * CIN + c) * NPIX;

        if (!anywz) {
            const int wd = tid >> 5, l = tid & 31;
            const int half = wd & 1, sub = wd >> 1;
            const int r0 = rc * 56 + sub * 14;
            int colb; bool ldok;
            if (l < 28)      { colb = 112 * half + 4 * l;  ldok = true; }
            else if (l == 28){ colb = 112 * half + 112;    ldok = (half == 0); }
            else if (l == 29){ colb = 112 * half - 4;      ldok = (half == 1); }
            else             { colb = 0;                   ldok = false; }

            auto vget = [&](int row) -> float4 {
                if (ldok && row >= 0 && row < HW)
                    return __ldg((const float4*)(xp + row * HW + colb));
                return make_float4(1.f, 1.f, 1.f, 1.f);
            };
            auto nibof = [&](int row, float4 v) -> unsigned {
                if (!ldok || row < 0 || row >= HW) return 0xFu;
                return (v.x == 0.f ? 1u : 0u) | (v.y == 0.f ? 2u : 0u) |
                       (v.z == 0.f ? 4u : 0u) | (v.w == 0.f ? 8u : 0u);
            };

            int cnt0 = 0;
            float4 va = vget(r0 - 1);
            float4 vb = vget(r0);
            float4 vnext = vget(r0 + 1);
            unsigned zpm = zprow_calc(nibof(r0 - 1, va), l);
            unsigned zpc = zprow_calc(nibof(r0, vb), l);

            for (int r = r0; r < r0 + 14; r++) {
                float4 vd = vget(r + 2);
                unsigned zpn = zprow_calc(nibof(r + 1, vnext), l);
                unsigned z4 = zpm + zpc + zpn;   // byte-SIMD (max 9/byte)
                if (l < 28) {
                    if (z4 == 0) cnt0 += 4;
                    else {
                        #pragma unroll
                        for (int j = 0; j < 4; j++) {
                            unsigned bz = (z4 >> (8 * j)) & 0xFFu;
                            if (bz == 0) cnt0++;
                            else atomicAdd(&sbin[bz], 1);
                        }
                    }
                }
                zpm = zpc; zpc = zpn; vnext = vd;
            }
            if (l < 28 && cnt0) atomicAdd(&sbin[0], cnt0);
        } else {
            bool wz[KK];
            #pragma unroll
            for (int k = 0; k < KK; k++) wz[k] = (__ldg(&wgt[c * KK + k]) == 0.0f);
            const int col = tid;
            const int r0q = rc * 56;
            if (col < HW) {
                for (int row = r0q; row < r0q + 56; row++) {
                    int z = 0;
                    #pragma unroll
                    for (int kh = 0; kh < 3; kh++)
                        #pragma unroll
                        for (int kw = 0; kw < 3; kw++) {
                            int gy = row + kh - 1, gx = col + kw - 1;
                            bool zero = (gy < 0 || gy >= HW || gx < 0 || gx >= HW)
                                ? true
                                : (wz[kh * 3 + kw] || __ldg(&xp[gy * HW + gx]) == 0.0f);
                            z += zero ? 1 : 0;
                        }
                    atomicAdd(&sbin[z], 1);
                }
            }
        }

        __syncthreads();
        if (tid < NBINS && sbin[tid])
            atomicAdd(&g_hist_i[c * NBINS + tid], sbin[tid]);
        return;
    }

    // ================= CONV BLOCK =================
    uint32_t (*sA)[4224] = sm.c.sA;
    int*   tab   = sm.c.tab;
    float* sbias = sm.c.sbias;

    for (int i = tid; i < KTOT; i += 256) {
        int ci = i / 9, tap = i - ci * 9;
        int dh = tap / 3, dw = tap - dh * 3;           // 0..2
        tab[i] = ci * NPIX + dh * HW + dw;             // offset from (hm-1, wm-1)
    }
    if (tid < COUT) sbias[tid] = __ldg(&bias[tid]);

    const int b    = cidx / NTILE;
    const int pix0 = (cidx % NTILE) * TILE_M;
    const float* xb = x + (size_t)b * CIN * NPIX;

    // ---- writer slot state ----
    const int lane_s = tid & 31;
    const int ks_s   = (tid >> 5) & 3;
    const int g_s    = lane_s >> 2;
    const int th_s   = lane_s & 3;
    const int kkoff  = ks_s * 8 + th_s;
    const int mtb    = tid >> 7;

    const float* ptr[8];
    unsigned tmask[8];           // 9-bit tap validity per slot
    #pragma unroll
    for (int i = 0; i < 4; i++) {
        #pragma unroll
        for (int half = 0; half < 2; half++) {
            int s  = i * 2 + half;
            int m  = (mtb + 2 * i) * 16 + g_s + half * 8;
            int pm = pix0 + m;
            int hm = pm / HW, wm = pm - hm * HW;
            ptr[s] = xb + hm * HW + wm - (HW + 1);
            int mk = 2 | 16;
            if (hm > 0)      mk |= 1;
            if (hm + 1 < HW) mk |= 4;
            if (wm > 0)      mk |= 8;
            if (wm + 1 < HW) mk |= 32;
            unsigned tm = 0;
            #pragma unroll
            for (int t = 0; t < 9; t++) {
                int dh = t / 3, dw = t - dh * 3;
                if (((mk >> dh) & 1) && ((mk >> (3 + dw)) & 1)) tm |= 1u << t;
            }
            tmask[s] = tm;
        }
    }
    const int base0 = ((mtb * 4 + ks_s) * 32 + lane_s) * 4;

    __syncthreads();

    uint32_t areg[4][4];
    auto loadA = [&](int c, int ta, int tb) {
        const int k0 = c * KC;
        const int offa = tab[k0 + kkoff];
        const int offb = tab[k0 + kkoff + 4];
        #pragma unroll
        for (int s = 0; s < 8; s++) {
            bool oka = (tmask[s] >> ta) & 1u;
            bool okb = (tmask[s] >> tb) & 1u;
            float va = oka ? __ldg(ptr[s] + offa) : 0.0f;
            float vb = okb ? __ldg(ptr[s] + offb) : 0.0f;
            const int i = s >> 1, half = s & 1;
            areg[i][half]     = f2tf32(va);
            areg[i][2 + half] = f2tf32(vb);
        }
    };

    const int w    = tid >> 5;
    const int lane = tid & 31;
    const int wm2  = (w & 3) * 2;
    const int wn4  = (w >> 2) * 4;

    float d[2][4][4];
    #pragma unroll
    for (int mt = 0; mt < 2; mt++)
        #pragma unroll
        for (int nt = 0; nt < 4; nt++)
            #pragma unroll
            for (int k = 0; k < 4; k++) d[mt][nt][k] = 0.0f;

    int ta = kkoff % 9;
    int tb = (ta + 4 >= 9) ? ta - 5 : ta + 4;
    loadA(0, ta, tb);

    for (int c = 0; c < NCHUNK; c++) {
        const int p = c & 1;
        #pragma unroll
        for (int i = 0; i < 4; i++)
            *(uint4*)&sA[p][base0 + i * 1024] =
                make_uint4(areg[i][0], areg[i][1], areg[i][2], areg[i][3]);
        __syncthreads();
        if (c + 1 < NCHUNK) {
            ta = (ta + 5 >= 9) ? ta - 4 : ta + 5;
            tb = (ta + 4 >= 9) ? ta - 5 : ta + 4;
            loadA(c + 1, ta, tb);
        }

        const uint2* bw = (const uint2*)g_wfrag + (size_t)(c * 8 + wn4) * 128;
        #pragma unroll
        for (int ks = 0; ks < 4; ks++) {
            uint4 a0 = *(const uint4*)&sA[p][((wm2 * 4 + ks) * 32 + lane) * 4];
            uint4 a1 = *(const uint4*)&sA[p][(((wm2 + 1) * 4 + ks) * 32 + lane) * 4];
            #pragma unroll
            for (int nt = 0; nt < 4; nt++) {
                uint2 bv = __ldg(&bw[(nt * 4 + ks) * 32 + lane]);
                MMA_TF32(d[0][nt], a0, bv);
                MMA_TF32(d[1][nt], a1, bv);
            }
        }
    }

    // ---- epilogue: stage via smem for coalesced 128B stores ----
    __syncthreads();                     // all frag reads done; safe to reuse sA
    float* E = (float*)&sA[0][0];        // 8448 floats avail, need 63*132+127
    const int rbase = (w & 3) * 32 + (lane >> 2);
    const int cbase = (w >> 2) * 32 + (lane & 3) * 2;
    #pragma unroll
    for (int mt = 0; mt < 2; mt++) {
        #pragma unroll
        for (int nt = 0; nt < 4; nt++) {
            int r0 = rbase + mt * 16;
            int c0 = cbase + nt * 8;
            E[c0 * ESTRIDE + r0]           = d[mt][nt][0];
            E[(c0 + 1) * ESTRIDE + r0]     = d[mt][nt][1];
            E[c0 * ESTRIDE + r0 + 8]       = d[mt][nt][2];
            E[(c0 + 1) * ESTRIDE + r0 + 8] = d[mt][nt][3];
        }
    }
    __syncthreads();

    float* yb = y + (size_t)b * COUT * NPIX + pix0;
    const int p4 = lane * 4;
    #pragma unroll
    for (int i = 0; i < 8; i++) {
        int co = w * 8 + i;
        float4 v = *(const float4*)&E[co * ESTRIDE + p4];
        float bv = sbias[co];
        v.x += bv; v.y += bv; v.z += bv; v.w += bv;
        *(float4*)&yb[(size_t)co * NPIX + p4] = v;
    }
}

__global__ void hist_write_kernel(float* __restrict__ out_hist) {
    int t = threadIdx.x;
    if (t < CIN * NBINS) out_hist[t] = (float)g_hist_i[t];
}

// ---------------------------------------------------------------------------
extern "C" void kernel_launch(void* const* d_in, const int* in_sizes, int n_in,
                              void* d_out, int out_size) {
    const float* x    = (const float*)d_in[0];   // (4,64,224,224)
    const float* wgt  = (const float*)d_in[1];   // (64,64,3,3)
    const float* bias = (const float*)d_in[2];   // (64,)
    float* y    = (float*)d_out;
    float* hist = (float*)d_out + (size_t)Y_ELEMS;

    repack_w_kernel<<<(NCHUNK * 2048 + 255) / 256, 256>>>(wgt);
    fused_kernel<<<NBLK, 256>>>(x, wgt, bias, y);
    hist_write_kernel<<<1, CIN * NBINS>>>(hist);
}

// round 6
// speedup vs baseline: 1.5871x; 1.5871x over previous
#include <cuda_runtime.h>
#include <cstdint>

#define BATCH 4
#define CIN   64
#define COUT  64
#define HW    224
#define NPIX  (HW * HW)          // 50176
#define KK    9
#define NBINS 10
#define KTOT  (CIN * KK)         // 576
#define KC    32
#define NCHUNK (KTOT / KC)       // 18
#define TILE_M 128
#define NTILE (NPIX / TILE_M)    // 392
#define NCONV (BATCH * NTILE)    // 1568
#define Y_ELEMS (BATCH * COUT * NPIX)
#define ESTRIDE 132              // epilogue smem stride (conflict-free)

// B fragments, tf32 bits, layout [chunk][nt 8][ks 4][lane 32][2]
__device__ uint32_t g_wfrag[NCHUNK * 2048];
__device__ int g_hist_i[CIN * NBINS];

__device__ __forceinline__ uint32_t f2tf32(float v) {
    uint32_t u;
    asm("cvt.rna.tf32.f32 %0, %1;" : "=r"(u) : "f"(v));
    return u;
}

#define MMA_TF32(d, a, b) \
    asm volatile("mma.sync.aligned.m16n8k8.row.col.f32.tf32.tf32.f32 " \
        "{%0,%1,%2,%3}, {%4,%5,%6,%7}, {%8,%9}, {%0,%1,%2,%3};" \
        : "+f"((d)[0]), "+f"((d)[1]), "+f"((d)[2]), "+f"((d)[3]) \
        : "r"((a).x), "r"((a).y), "r"((a).z), "r"((a).w), \
          "r"((b).x), "r"((b).y))

// ---------------------------------------------------------------------------
// Repack W (64, 576) -> fragment order (tf32-rounded) + zero hist scratch.
// ---------------------------------------------------------------------------
__global__ void repack_w_kernel(const float* __restrict__ w) {
    int idx = blockIdx.x * blockDim.x + threadIdx.x;
    if (idx < NCHUNK * 2048) {
        int pair = idx & 1;
        int lane = (idx >> 1) & 31;
        int ks   = (idx >> 6) & 3;
        int nt   = (idx >> 8) & 7;
        int c    = idx >> 11;
        int n = nt * 8 + (lane >> 2);
        int k = c * 32 + ks * 8 + (lane & 3) + pair * 4;
        g_wfrag[idx] = f2tf32(__ldg(&w[n * KTOT + k]));
    }
    if (idx < CIN * NBINS) g_hist_i[idx] = 0;
}

// ---------------------------------------------------------------------------
// Implicit-GEMM conv via mma.sync tf32 (m16n8k8).
// CTA: 128 pixels x 64 couts. 8 warps: (w&3) -> M block of 32, (w>>2) -> N 32.
// ---------------------------------------------------------------------------
__global__ __launch_bounds__(256, 2)
void conv_mma_kernel(const float* __restrict__ x,
                     const float* __restrict__ bias,
                     float* __restrict__ y) {
    __shared__ __align__(16) uint32_t sA[2][4224];   // frag A dbuf; epilogue stage
    __shared__ int   tab[KTOT];
    __shared__ float sbias[COUT];

    const int tid = threadIdx.x;

    for (int i = tid; i < KTOT; i += 256) {
        int ci = i / 9, tap = i - ci * 9;
        int dh = tap / 3, dw = tap - dh * 3;           // 0..2
        tab[i] = ci * NPIX + dh * HW + dw;             // offset from (hm-1, wm-1)
    }
    if (tid < COUT) sbias[tid] = __ldg(&bias[tid]);

    const int b    = blockIdx.x / NTILE;
    const int pix0 = (blockIdx.x % NTILE) * TILE_M;
    const float* xb = x + (size_t)b * CIN * NPIX;

    // ---- writer slot state ----
    const int lane_s = tid & 31;
    const int ks_s   = (tid >> 5) & 3;
    const int g_s    = lane_s >> 2;
    const int th_s   = lane_s & 3;
    const int kkoff  = ks_s * 8 + th_s;
    const int mtb    = tid >> 7;

    const float* ptr[8];
    unsigned tmask[8];           // 9-bit tap validity per slot
    #pragma unroll
    for (int i = 0; i < 4; i++) {
        #pragma unroll
        for (int half = 0; half < 2; half++) {
            int s  = i * 2 + half;
            int m  = (mtb + 2 * i) * 16 + g_s + half * 8;
            int pm = pix0 + m;
            int hm = pm / HW, wm = pm - hm * HW;
            ptr[s] = xb + hm * HW + wm - (HW + 1);
            int mk = 2 | 16;
            if (hm > 0)      mk |= 1;
            if (hm + 1 < HW) mk |= 4;
            if (wm > 0)      mk |= 8;
            if (wm + 1 < HW) mk |= 32;
            unsigned tm = 0;
            #pragma unroll
            for (int t = 0; t < 9; t++) {
                int dh = t / 3, dw = t - dh * 3;
                if (((mk >> dh) & 1) && ((mk >> (3 + dw)) & 1)) tm |= 1u << t;
            }
            tmask[s] = tm;
        }
    }
    const int base0 = ((mtb * 4 + ks_s) * 32 + lane_s) * 4;

    __syncthreads();

    uint32_t areg[4][4];
    auto loadA = [&](int c, int ta, int tb) {
        const int k0 = c * KC;
        const int offa = tab[k0 + kkoff];
        const int offb = tab[k0 + kkoff + 4];
        #pragma unroll
        for (int s = 0; s < 8; s++) {
            bool oka = (tmask[s] >> ta) & 1u;
            bool okb = (tmask[s] >> tb) & 1u;
            float va = oka ? __ldg(ptr[s] + offa) : 0.0f;
            float vb = okb ? __ldg(ptr[s] + offb) : 0.0f;
            const int i = s >> 1, half = s & 1;
            areg[i][half]     = f2tf32(va);
            areg[i][2 + half] = f2tf32(vb);
        }
    };

    const int w    = tid >> 5;
    const int lane = tid & 31;
    const int wm2  = (w & 3) * 2;
    const int wn4  = (w >> 2) * 4;

    float d[2][4][4];
    #pragma unroll
    for (int mt = 0; mt < 2; mt++)
        #pragma unroll
        for (int nt = 0; nt < 4; nt++)
            #pragma unroll
            for (int k = 0; k < 4; k++) d[mt][nt][k] = 0.0f;

    int ta = kkoff % 9;
    int tb = (ta + 4 >= 9) ? ta - 5 : ta + 4;
    loadA(0, ta, tb);

    for (int c = 0; c < NCHUNK; c++) {
        const int p = c & 1;
        #pragma unroll
        for (int i = 0; i < 4; i++)
            *(uint4*)&sA[p][base0 + i * 1024] =
                make_uint4(areg[i][0], areg[i][1], areg[i][2], areg[i][3]);
        __syncthreads();
        if (c + 1 < NCHUNK) {
            ta = (ta + 5 >= 9) ? ta - 4 : ta + 5;
            tb = (ta + 4 >= 9) ? ta - 5 : ta + 4;
            loadA(c + 1, ta, tb);
        }

        const uint2* bw = (const uint2*)g_wfrag + (size_t)(c * 8 + wn4) * 128;
        #pragma unroll
        for (int ks = 0; ks < 4; ks++) {
            uint4 a0 = *(const uint4*)&sA[p][((wm2 * 4 + ks) * 32 + lane) * 4];
            uint4 a1 = *(const uint4*)&sA[p][(((wm2 + 1) * 4 + ks) * 32 + lane) * 4];
            #pragma unroll
            for (int nt = 0; nt < 4; nt++) {
                uint2 bv = __ldg(&bw[(nt * 4 + ks) * 32 + lane]);
                MMA_TF32(d[0][nt], a0, bv);
                MMA_TF32(d[1][nt], a1, bv);
            }
        }
    }

    // ---- epilogue: stage via smem for coalesced 128B stores ----
    __syncthreads();                     // all frag reads done; safe to reuse sA
    float* E = (float*)&sA[0][0];        // 8448 floats, need 63*132+127 = 8443
    const int rbase = (w & 3) * 32 + (lane >> 2);
    const int cbase = (w >> 2) * 32 + (lane & 3) * 2;
    #pragma unroll
    for (int mt = 0; mt < 2; mt++) {
        #pragma unroll
        for (int nt = 0; nt < 4; nt++) {
            int r0 = rbase + mt * 16;
            int c0 = cbase + nt * 8;
            E[c0 * ESTRIDE + r0]           = d[mt][nt][0];
            E[(c0 + 1) * ESTRIDE + r0]     = d[mt][nt][1];
            E[c0 * ESTRIDE + r0 + 8]       = d[mt][nt][2];
            E[(c0 + 1) * ESTRIDE + r0 + 8] = d[mt][nt][3];
        }
    }
    __syncthreads();

    float* yb = y + (size_t)b * COUT * NPIX + pix0;
    const int p4 = lane * 4;
    #pragma unroll
    for (int i = 0; i < 8; i++) {
        int co = w * 8 + i;
        float4 v = *(const float4*)&E[co * ESTRIDE + p4];
        float bv = sbias[co];
        v.x += bv; v.y += bv; v.z += bv; v.w += bv;
        *(float4*)&yb[(size_t)co * NPIX + p4] = v;
    }
}

// ---------------------------------------------------------------------------
// Histogram: warp-ballot byte-SIMD separable window-sum. Tiny smem footprint.
// product(b,c,ho,wo,k)==0 iff pad || x==0 || w[0,c,k]==0.
// ---------------------------------------------------------------------------
__device__ __forceinline__ unsigned zprow_calc(unsigned nib, int l) {
    unsigned nl = __shfl_sync(0xFFFFFFFFu, nib, (l == 0) ? 29 : (l - 1));
    unsigned nr = __shfl_sync(0xFFFFFFFFu, nib, (l == 27) ? 28 : ((l + 1) & 31));
    unsigned ext = ((nl >> 3) & 1u) | (nib << 1) | ((nr & 1u) << 5);
    unsigned z0 = __popc(ext & 7u);
    unsigned z1 = __popc((ext >> 1) & 7u);
    unsigned z2 = __popc((ext >> 2) & 7u);
    unsigned z3 = __popc((ext >> 3) & 7u);
    return z0 | (z1 << 8) | (z2 << 16) | (z3 << 24);
}

__global__ __launch_bounds__(256)
void hist_count_kernel(const float* __restrict__ x, const float* __restrict__ w) {
    const int bid = blockIdx.x;
    const int rc = bid & 3;
    const int c  = (bid >> 2) & 63;
    const int b  = bid >> 8;

    __shared__ int sbin[NBINS];
    const int tid = threadIdx.x;
    if (tid < NBINS) sbin[tid] = 0;

    bool anywz = false;
    #pragma unroll
    for (int k = 0; k < KK; k++) anywz |= (__ldg(&w[c * KK + k]) == 0.0f);
    __syncthreads();

    const float* xp = x + (size_t)(b * CIN + c) * NPIX;

    if (!anywz) {
        const int wd = tid >> 5, l = tid & 31;
        const int half = wd & 1, sub = wd >> 1;
        const int r0 = rc * 56 + sub * 14;
        int colb; bool ldok;
        if (l < 28)      { colb = 112 * half + 4 * l;  ldok = true; }
        else if (l == 28){ colb = 112 * half + 112;    ldok = (half == 0); }
        else if (l == 29){ colb = 112 * half - 4;      ldok = (half == 1); }
        else             { colb = 0;                   ldok = false; }

        auto vget = [&](int row) -> float4 {
            if (ldok && row >= 0 && row < HW)
                return __ldg((const float4*)(xp + row * HW + colb));
            return make_float4(1.f, 1.f, 1.f, 1.f);
        };
        auto nibof = [&](int row, float4 v) -> unsigned {
            if (!ldok || row < 0 || row >= HW) return 0xFu;
            return (v.x == 0.f ? 1u : 0u) | (v.y == 0.f ? 2u : 0u) |
                   (v.z == 0.f ? 4u : 0u) | (v.w == 0.f ? 8u : 0u);
        };

        int cnt0 = 0;
        float4 va = vget(r0 - 1);
        float4 vb = vget(r0);
        float4 vnext = vget(r0 + 1);
        unsigned zpm = zprow_calc(nibof(r0 - 1, va), l);
        unsigned zpc = zprow_calc(nibof(r0, vb), l);

        for (int r = r0; r < r0 + 14; r++) {
            float4 vd = vget(r + 2);
            unsigned zpn = zprow_calc(nibof(r + 1, vnext), l);
            unsigned z4 = zpm + zpc + zpn;   // byte-SIMD (max 9/byte)
            if (l < 28) {
                if (z4 == 0) cnt0 += 4;
                else {
                    #pragma unroll
                    for (int j = 0; j < 4; j++) {
                        unsigned bz = (z4 >> (8 * j)) & 0xFFu;
                        if (bz == 0) cnt0++;
                        else atomicAdd(&sbin[bz], 1);
                    }
                }
            }
            zpm = zpc; zpc = zpn; vnext = vd;
        }
        if (l < 28 && cnt0) atomicAdd(&sbin[0], cnt0);
    } else {
        bool wz[KK];
        #pragma unroll
        for (int k = 0; k < KK; k++) wz[k] = (__ldg(&w[c * KK + k]) == 0.0f);
        const int col = tid;
        const int r0q = rc * 56;
        if (col < HW) {
            for (int row = r0q; row < r0q + 56; row++) {
                int z = 0;
                #pragma unroll
                for (int kh = 0; kh < 3; kh++)
                    #pragma unroll
                    for (int kw = 0; kw < 3; kw++) {
                        int gy = row + kh - 1, gx = col + kw - 1;
                        bool zero = (gy < 0 || gy >= HW || gx < 0 || gx >= HW)
                            ? true
                            : (wz[kh * 3 + kw] || __ldg(&xp[gy * HW + gx]) == 0.0f);
                        z += zero ? 1 : 0;
                    }
                atomicAdd(&sbin[z], 1);
            }
        }
    }

    __syncthreads();
    if (tid < NBINS && sbin[tid])
        atomicAdd(&g_hist_i[c * NBINS + tid], sbin[tid]);
}

__global__ void hist_write_kernel(float* __restrict__ out_hist) {
    int t = threadIdx.x;
    if (t < CIN * NBINS) out_hist[t] = (float)g_hist_i[t];
}

// ---------------------------------------------------------------------------
extern "C" void kernel_launch(void* const* d_in, const int* in_sizes, int n_in,
                              void* d_out, int out_size) {
    const float* x    = (const float*)d_in[0];   // (4,64,224,224)
    const float* wgt  = (const float*)d_in[1];   // (64,64,3,3)
    const float* bias = (const float*)d_in[2];   // (64,)
    float* y    = (float*)d_out;
    float* hist = (float*)d_out + (size_t)Y_ELEMS;

    repack_w_kernel<<<(NCHUNK * 2048 + 255) / 256, 256>>>(wgt);
    conv_mma_kernel<<<NCONV, 256>>>(x, bias, y);
    hist_count_kernel<<<BATCH * CIN * 4, 256>>>(x, wgt);
    hist_write_kernel<<<1, CIN * NBINS>>>(hist);
}